// round 10
// baseline (speedup 1.0000x reference)
#include <cuda_runtime.h>

#define NQ   2048
#define NS   320
#define DIM  256
#define NWAY 20

typedef unsigned long long u64;

__device__ float g_qproj[NQ * DIM];
__device__ float g_sproj[NS * DIM];
__device__ float g_Ts[NS];

// ---- packed f32x2 helpers ----
__device__ __forceinline__ u64 add2(u64 a, u64 b) {
    u64 d; asm("add.rn.f32x2 %0, %1, %2;" : "=l"(d) : "l"(a), "l"(b)); return d;
}
__device__ __forceinline__ u64 fma2(u64 a, u64 b, u64 c) {
    u64 d; asm("fma.rn.f32x2 %0, %1, %2, %3;" : "=l"(d) : "l"(a), "l"(b), "l"(c)); return d;
}
__device__ __forceinline__ u64 dup2(float x) {
    u64 r; unsigned xi = __float_as_uint(x);
    asm("mov.b64 %0, {%1, %1};" : "=l"(r) : "r"(xi)); return r;
}
__device__ __forceinline__ float lo2(u64 v) { return __uint_as_float((unsigned)v); }
__device__ __forceinline__ float hi2(u64 v) { return __uint_as_float((unsigned)(v >> 32)); }

__device__ __forceinline__ void cpa16(void* dst, const void* src) {
    unsigned sa = (unsigned)__cvta_generic_to_shared(dst);
    asm volatile("cp.async.cg.shared.global [%0], [%1], 16;" :: "r"(sa), "l"(src));
}

// ---------------------------------------------------------------------------
// Kernel A: projections — R6 version verbatim (measured 16.1us)
// ---------------------------------------------------------------------------
#define PBK   64
#define PADA  65
#define PADB  68
#define ASTG  (PBK * PADA)
#define BSTG  (PBK * PADB)

__global__ void __launch_bounds__(256) proj_kernel(
    const float* __restrict__ support, const float* __restrict__ query,
    const float* __restrict__ W1, const float* __restrict__ b1)
{
    extern __shared__ __align__(16) unsigned char psm[];
    u64*   AsD = (u64*)psm;
    float* Bs  = (float*)(AsD + 2 * ASTG);

    const int tile_n = blockIdx.x;
    const int tile_m = blockIdx.y;
    const bool is_sup = (tile_m >= NQ / 64);

    const float* Amat;
    const float* Bmat;
    int m0;
    if (is_sup) { m0 = (tile_m - NQ / 64) * 64; Amat = support; Bmat = W1 + DIM * DIM; }
    else        { m0 = tile_m * 64;             Amat = query;   Bmat = W1; }
    const int n0 = tile_n * 64;

    const int tid = threadIdx.x;
    const int tx = tid & 15;
    const int ty = tid >> 4;

    const int t_m = tid >> 2;
    const int t_k = (tid & 3) * 4;

    const int b_row = tid >> 2;
    const int b_q   = tid & 3;

    const float* Arow = Amat + (m0 + t_m) * DIM;
    const float* Brow = Bmat + b_row * DIM + n0;

    u64 acc[4][2];
    #pragma unroll
    for (int i = 0; i < 4; i++) { acc[i][0] = 0ull; acc[i][1] = 0ull; }

    float4 areg[4];

    #pragma unroll
    for (int u = 0; u < 4; u++)
        areg[u] = *(const float4*)(Arow + t_k + u * 16);
    #pragma unroll
    for (int u = 0; u < 4; u++) {
        const int kk = t_k + u * 16;
        AsD[(kk + 0) * PADA + t_m] = dup2(areg[u].x);
        AsD[(kk + 1) * PADA + t_m] = dup2(areg[u].y);
        AsD[(kk + 2) * PADA + t_m] = dup2(areg[u].z);
        AsD[(kk + 3) * PADA + t_m] = dup2(areg[u].w);
    }
    #pragma unroll
    for (int u = 0; u < 4; u++) {
        const int c4 = b_q + u * 4;
        cpa16(&Bs[b_row * PADB + c4 * 4], Brow + c4 * 4);
    }
    asm volatile("cp.async.commit_group;");

    #pragma unroll
    for (int s = 0; s < 4; s++) {
        const int buf = s & 1;
        asm volatile("cp.async.wait_group 0;");
        __syncthreads();

        if (s < 3) {
            const int k0n = (s + 1) * PBK;
            #pragma unroll
            for (int u = 0; u < 4; u++)
                areg[u] = *(const float4*)(Arow + k0n + t_k + u * 16);
            #pragma unroll
            for (int u = 0; u < 4; u++) {
                const int c4 = b_q + u * 4;
                cpa16(&Bs[(buf ^ 1) * BSTG + b_row * PADB + c4 * 4],
                      Brow + k0n * DIM + c4 * 4);
            }
            asm volatile("cp.async.commit_group;");
        }

        const u64*   aB = AsD + buf * ASTG + ty * 4;
        const float* bB = Bs + buf * BSTG + tx * 4;

        #pragma unroll 8
        for (int k = 0; k < PBK; k++) {
            ulonglong2 b = *(const ulonglong2*)(bB + k * PADB);
            u64 a0 = aB[k * PADA + 0];
            u64 a1 = aB[k * PADA + 1];
            u64 a2 = aB[k * PADA + 2];
            u64 a3 = aB[k * PADA + 3];
            acc[0][0] = fma2(a0, b.x, acc[0][0]); acc[0][1] = fma2(a0, b.y, acc[0][1]);
            acc[1][0] = fma2(a1, b.x, acc[1][0]); acc[1][1] = fma2(a1, b.y, acc[1][1]);
            acc[2][0] = fma2(a2, b.x, acc[2][0]); acc[2][1] = fma2(a2, b.y, acc[2][1]);
            acc[3][0] = fma2(a3, b.x, acc[3][0]); acc[3][1] = fma2(a3, b.y, acc[3][1]);
        }

        if (s < 3) {
            u64* dst = AsD + (buf ^ 1) * ASTG;
            #pragma unroll
            for (int u = 0; u < 4; u++) {
                const int kk = t_k + u * 16;
                dst[(kk + 0) * PADA + t_m] = dup2(areg[u].x);
                dst[(kk + 1) * PADA + t_m] = dup2(areg[u].y);
                dst[(kk + 2) * PADA + t_m] = dup2(areg[u].z);
                dst[(kk + 3) * PADA + t_m] = dup2(areg[u].w);
            }
        }
    }

    #pragma unroll
    for (int i = 0; i < 4; i++) {
        const int m = m0 + ty * 4 + i;
        float v[4] = { lo2(acc[i][0]), hi2(acc[i][0]), lo2(acc[i][1]), hi2(acc[i][1]) };
        #pragma unroll
        for (int j = 0; j < 4; j++) {
            const int n = n0 + tx * 4 + j;
            if (is_sup) g_sproj[m * DIM + n] = v[j] + __ldg(b1 + n);
            else        g_qproj[m * DIM + n] = v[j];
        }
    }
}

// ---------------------------------------------------------------------------
// Kernel A2: Ts[s] = sum_d g_sproj[s,d] * W2[d]
// ---------------------------------------------------------------------------
__global__ void __launch_bounds__(256) rowsum_kernel(const float* __restrict__ W2)
{
    const int warp = threadIdx.x >> 5, lane = threadIdx.x & 31;
    const int r0 = blockIdx.x * 32 + warp * 4;
    const float4* w4 = (const float4*)W2;
    float4 w1 = w4[lane * 2], w2v = w4[lane * 2 + 1];
    #pragma unroll
    for (int r = 0; r < 4; r++) {
        const int row = r0 + r;
        const float4* sp4 = (const float4*)(g_sproj + row * DIM);
        float4 s1 = sp4[lane * 2], s2 = sp4[lane * 2 + 1];
        float t = s1.x * w1.x + s1.y * w1.y + s1.z * w1.z + s1.w * w1.w
                + s2.x * w2v.x + s2.y * w2v.y + s2.z * w2v.z + s2.w * w2v.w;
        #pragma unroll
        for (int o = 16; o > 0; o >>= 1) t += __shfl_xor_sync(0xffffffffu, t, o);
        if (lane == 0) g_Ts[row] = t;
    }
}

// ---------------------------------------------------------------------------
// Kernel B: warp = 16-dim d-team, all 16 q in TWO passes of 8 (reg pressure).
// Atomic-free: per-warp partials -> pbuf -> tree reduce -> part.
//   score'[q,s] = 0.5*(Ts[s] + sum_d |qp+sp| * W2[d])
// ---------------------------------------------------------------------------
#define QB 16
#define TPB 512
#define SPAD 260
#define CHUNKF 8320
#define ABSMASK 0x7FFFFFFF7FFFFFFFull

__device__ __forceinline__ void prefetch_chunk(float* buf, int c, int tid) {
    #pragma unroll
    for (int i = 0; i < 4; i++) {
        int f   = tid + i * TPB;
        int row = f >> 6;
        int c4  = f & 63;
        cpa16(buf + row * SPAD + c4 * 4, g_sproj + (c * 32 + row) * DIM + c4 * 4);
    }
    asm volatile("cp.async.commit_group;");
}

__global__ void __launch_bounds__(TPB, 1) score_kernel(
    const int* __restrict__ labels, const float* __restrict__ W2,
    float* __restrict__ out)
{
    extern __shared__ float sm[];
    float* sp   = sm;                        // 2 * 8320
    float* qp   = sm + 2 * CHUNKF;           // 16*256 = 4096
    float* ts   = qp + QB * DIM;             // 320
    float* pbuf = ts + NS;                   // 16 warps * 16 q * 32 s = 8192
    float* part = pbuf + 16 * QB * 32;       // 16*320 = 5120
    float* sacc = part + QB * NS;            // 16*20 = 320
    int*   lbl  = (int*)(sacc + QB * NWAY);  // 320

    const int tid  = threadIdx.x;
    const int warp = tid >> 5;               // = d-team, 16 dims each
    const int lane = tid & 31;               // = s within chunk
    const int qbase = blockIdx.x * QB;

    prefetch_chunk(sp, 0, tid);

    {
        const float4* qsrc = (const float4*)(g_qproj + qbase * DIM);
        float4* qpv = (float4*)qp;
        #pragma unroll
        for (int i = 0; i < 2; i++) qpv[tid + i * TPB] = qsrc[tid + i * TPB];
        if (tid < NS) { ts[tid] = g_Ts[tid]; lbl[tid] = labels[tid]; }
        if (tid < QB * NWAY) sacc[tid] = 0.f;
    }

    const int doff = warp * 16;              // this team's d-slice offset

    // hoist W2 slice: 4 x ulonglong2 (8 u64)
    u64 wx[4], wy[4];
    #pragma unroll
    for (int j = 0; j < 4; j++) {
        ulonglong2 wv = *(const ulonglong2*)(W2 + doff + j * 4);
        wx[j] = wv.x; wy[j] = wv.y;
    }

    for (int c = 0; c < 10; c++) {
        asm volatile("cp.async.wait_group 0;");
        __syncthreads();                      // chunk ready; pbuf free
        float* cur = sp + (c & 1) * CHUNKF;
        if (c + 1 < 10) prefetch_chunk(sp + ((c + 1) & 1) * CHUNKF, c + 1, tid);

        const ulonglong2* srow = (const ulonglong2*)(cur + lane * SPAD + doff);
        float* pw = pbuf + (warp * QB) * 32;

        #pragma unroll
        for (int h = 0; h < 2; h++) {         // q-halves: 8 q per pass
            u64 ax[8], ay[8];
            #pragma unroll
            for (int qq = 0; qq < 8; qq++) { ax[qq] = 0ull; ay[qq] = 0ull; }

            #pragma unroll
            for (int j = 0; j < 4; j++) {
                ulonglong2 sv = srow[j];
                #pragma unroll
                for (int qq = 0; qq < 8; qq++) {
                    const int q = h * 8 + qq;
                    ulonglong2 qv = *(const ulonglong2*)(qp + q * DIM + doff + j * 4);
                    u64 t;
                    t = add2(qv.x, sv.x) & ABSMASK; ax[qq] = fma2(t, wx[j], ax[qq]);
                    t = add2(qv.y, sv.y) & ABSMASK; ay[qq] = fma2(t, wy[j], ay[qq]);
                }
            }

            #pragma unroll
            for (int qq = 0; qq < 8; qq++)
                pw[(h * 8 + qq) * 32 + lane] =
                    (lo2(ax[qq]) + hi2(ax[qq])) + (lo2(ay[qq]) + hi2(ay[qq]));
        }

        __syncthreads();

        // tree reduce: thread (q = warp, sl = lane) sums 16 team partials
        {
            const int q = warp, sl = lane;
            float s = 0.f;
            #pragma unroll
            for (int w = 0; w < 16; w++)
                s += pbuf[(w * QB + q) * 32 + sl];
            part[q * NS + c * 32 + sl] = s;
        }
        // next top-of-loop __syncthreads separates reduce from next pbuf writes
    }
    __syncthreads();

    // ---- softmax: warp w owns q = w ----
    {
        const int q = warp;
        float v[10];
        #pragma unroll
        for (int c = 0; c < 10; c++)
            v[c] = 0.5f * (ts[c * 32 + lane] + part[q * NS + c * 32 + lane]);

        float m = v[0];
        #pragma unroll
        for (int c = 1; c < 10; c++) m = fmaxf(m, v[c]);
        #pragma unroll
        for (int o = 16; o > 0; o >>= 1)
            m = fmaxf(m, __shfl_xor_sync(0xffffffffu, m, o));

        float l = 0.f;
        #pragma unroll
        for (int c = 0; c < 10; c++) {
            float ev = __expf(v[c] - m);
            l += ev;
            atomicAdd(&sacc[q * NWAY + lbl[c * 32 + lane]], ev);
        }
        #pragma unroll
        for (int o = 16; o > 0; o >>= 1)
            l += __shfl_xor_sync(0xffffffffu, l, o);
        const float inv = 1.f / l;
        __syncwarp();

        if (lane < NWAY)
            out[(qbase + q) * NWAY + lane] = sacc[q * NWAY + lane] * inv;
    }
}

// ---------------------------------------------------------------------------
extern "C" void kernel_launch(void* const* d_in, const int* in_sizes, int n_in,
                              void* d_out, int out_size)
{
    (void)in_sizes; (void)n_in; (void)out_size;
    const float* support = (const float*)d_in[0];
    const float* query   = (const float*)d_in[1];
    const int*   labels  = (const int*)d_in[2];
    const float* W1      = (const float*)d_in[3];
    const float* b1      = (const float*)d_in[4];
    const float* W2      = (const float*)d_in[5];
    float* out = (float*)d_out;

    const int proj_smem = (2 * ASTG) * 8 + (2 * BSTG) * 4;  // 101376 B
    cudaFuncSetAttribute(proj_kernel,
                         cudaFuncAttributeMaxDynamicSharedMemorySize, proj_smem);
    proj_kernel<<<dim3(4, 37), 256, proj_smem>>>(support, query, W1, b1);

    rowsum_kernel<<<10, 256>>>(W2);

    const int smem_bytes =
        (2 * CHUNKF + QB * DIM + NS + 16 * QB * 32 + QB * NS + QB * NWAY) * 4
        + NS * 4;
    cudaFuncSetAttribute(score_kernel,
                         cudaFuncAttributeMaxDynamicSharedMemorySize, smem_bytes);
    score_kernel<<<NQ / QB, TPB, smem_bytes>>>(labels, W2, out);
}

// round 11
// speedup vs baseline: 1.0381x; 1.0381x over previous
#include <cuda_runtime.h>

#define NQ   2048
#define NS   320
#define DIM  256
#define NWAY 20

typedef unsigned long long u64;

__device__ float g_qproj[NQ * DIM];
__device__ float g_sproj[NS * DIM];

// ---- packed f32x2 helpers ----
__device__ __forceinline__ u64 add2(u64 a, u64 b) {
    u64 d; asm("add.rn.f32x2 %0, %1, %2;" : "=l"(d) : "l"(a), "l"(b)); return d;
}
__device__ __forceinline__ u64 fma2(u64 a, u64 b, u64 c) {
    u64 d; asm("fma.rn.f32x2 %0, %1, %2, %3;" : "=l"(d) : "l"(a), "l"(b), "l"(c)); return d;
}
__device__ __forceinline__ u64 dup2(float x) {
    u64 r; unsigned xi = __float_as_uint(x);
    asm("mov.b64 %0, {%1, %1};" : "=l"(r) : "r"(xi)); return r;
}
__device__ __forceinline__ float lo2(u64 v) { return __uint_as_float((unsigned)v); }
__device__ __forceinline__ float hi2(u64 v) { return __uint_as_float((unsigned)(v >> 32)); }

__device__ __forceinline__ void cpa16(void* dst, const void* src) {
    unsigned sa = (unsigned)__cvta_generic_to_shared(dst);
    asm volatile("cp.async.cg.shared.global [%0], [%1], 16;" :: "r"(sa), "l"(src));
}

// ---------------------------------------------------------------------------
// Kernel A: projections — R6 version verbatim (measured 16.1us)
// ---------------------------------------------------------------------------
#define PBK   64
#define PADA  65
#define PADB  68
#define ASTG  (PBK * PADA)
#define BSTG  (PBK * PADB)

__global__ void __launch_bounds__(256) proj_kernel(
    const float* __restrict__ support, const float* __restrict__ query,
    const float* __restrict__ W1, const float* __restrict__ b1)
{
    extern __shared__ __align__(16) unsigned char psm[];
    u64*   AsD = (u64*)psm;
    float* Bs  = (float*)(AsD + 2 * ASTG);

    const int tile_n = blockIdx.x;
    const int tile_m = blockIdx.y;
    const bool is_sup = (tile_m >= NQ / 64);

    const float* Amat;
    const float* Bmat;
    int m0;
    if (is_sup) { m0 = (tile_m - NQ / 64) * 64; Amat = support; Bmat = W1 + DIM * DIM; }
    else        { m0 = tile_m * 64;             Amat = query;   Bmat = W1; }
    const int n0 = tile_n * 64;

    const int tid = threadIdx.x;
    const int tx = tid & 15;
    const int ty = tid >> 4;

    const int t_m = tid >> 2;
    const int t_k = (tid & 3) * 4;

    const int b_row = tid >> 2;
    const int b_q   = tid & 3;

    const float* Arow = Amat + (m0 + t_m) * DIM;
    const float* Brow = Bmat + b_row * DIM + n0;

    u64 acc[4][2];
    #pragma unroll
    for (int i = 0; i < 4; i++) { acc[i][0] = 0ull; acc[i][1] = 0ull; }

    float4 areg[4];

    #pragma unroll
    for (int u = 0; u < 4; u++)
        areg[u] = *(const float4*)(Arow + t_k + u * 16);
    #pragma unroll
    for (int u = 0; u < 4; u++) {
        const int kk = t_k + u * 16;
        AsD[(kk + 0) * PADA + t_m] = dup2(areg[u].x);
        AsD[(kk + 1) * PADA + t_m] = dup2(areg[u].y);
        AsD[(kk + 2) * PADA + t_m] = dup2(areg[u].z);
        AsD[(kk + 3) * PADA + t_m] = dup2(areg[u].w);
    }
    #pragma unroll
    for (int u = 0; u < 4; u++) {
        const int c4 = b_q + u * 4;
        cpa16(&Bs[b_row * PADB + c4 * 4], Brow + c4 * 4);
    }
    asm volatile("cp.async.commit_group;");

    #pragma unroll
    for (int s = 0; s < 4; s++) {
        const int buf = s & 1;
        asm volatile("cp.async.wait_group 0;");
        __syncthreads();

        if (s < 3) {
            const int k0n = (s + 1) * PBK;
            #pragma unroll
            for (int u = 0; u < 4; u++)
                areg[u] = *(const float4*)(Arow + k0n + t_k + u * 16);
            #pragma unroll
            for (int u = 0; u < 4; u++) {
                const int c4 = b_q + u * 4;
                cpa16(&Bs[(buf ^ 1) * BSTG + b_row * PADB + c4 * 4],
                      Brow + k0n * DIM + c4 * 4);
            }
            asm volatile("cp.async.commit_group;");
        }

        const u64*   aB = AsD + buf * ASTG + ty * 4;
        const float* bB = Bs + buf * BSTG + tx * 4;

        #pragma unroll 8
        for (int k = 0; k < PBK; k++) {
            ulonglong2 b = *(const ulonglong2*)(bB + k * PADB);
            u64 a0 = aB[k * PADA + 0];
            u64 a1 = aB[k * PADA + 1];
            u64 a2 = aB[k * PADA + 2];
            u64 a3 = aB[k * PADA + 3];
            acc[0][0] = fma2(a0, b.x, acc[0][0]); acc[0][1] = fma2(a0, b.y, acc[0][1]);
            acc[1][0] = fma2(a1, b.x, acc[1][0]); acc[1][1] = fma2(a1, b.y, acc[1][1]);
            acc[2][0] = fma2(a2, b.x, acc[2][0]); acc[2][1] = fma2(a2, b.y, acc[2][1]);
            acc[3][0] = fma2(a3, b.x, acc[3][0]); acc[3][1] = fma2(a3, b.y, acc[3][1]);
        }

        if (s < 3) {
            u64* dst = AsD + (buf ^ 1) * ASTG;
            #pragma unroll
            for (int u = 0; u < 4; u++) {
                const int kk = t_k + u * 16;
                dst[(kk + 0) * PADA + t_m] = dup2(areg[u].x);
                dst[(kk + 1) * PADA + t_m] = dup2(areg[u].y);
                dst[(kk + 2) * PADA + t_m] = dup2(areg[u].z);
                dst[(kk + 3) * PADA + t_m] = dup2(areg[u].w);
            }
        }
    }

    #pragma unroll
    for (int i = 0; i < 4; i++) {
        const int m = m0 + ty * 4 + i;
        float v[4] = { lo2(acc[i][0]), hi2(acc[i][0]), lo2(acc[i][1]), hi2(acc[i][1]) };
        #pragma unroll
        for (int j = 0; j < 4; j++) {
            const int n = n0 + tx * 4 + j;
            if (is_sup) g_sproj[m * DIM + n] = v[j] + __ldg(b1 + n);
            else        g_qproj[m * DIM + n] = v[j];
        }
    }
}

// ---------------------------------------------------------------------------
// Kernel B: warp = 16-dim d-team, 16 q in two passes of 8.
// Ts FUSED: each warp also accumulates sum_d(slice) sp*W2 per s from the
// already-loaded srow values; reduced via tbuf by warp 0. rowsum kernel gone.
//   score'[q,s] = 0.5*(Ts[s] + sum_d |qp+sp| * W2[d])
// ---------------------------------------------------------------------------
#define QB 16
#define TPB 512
#define SPAD 260
#define CHUNKF 8320
#define ABSMASK 0x7FFFFFFF7FFFFFFFull

__device__ __forceinline__ void prefetch_chunk(float* buf, int c, int tid) {
    #pragma unroll
    for (int i = 0; i < 4; i++) {
        int f   = tid + i * TPB;
        int row = f >> 6;
        int c4  = f & 63;
        cpa16(buf + row * SPAD + c4 * 4, g_sproj + (c * 32 + row) * DIM + c4 * 4);
    }
    asm volatile("cp.async.commit_group;");
}

__global__ void __launch_bounds__(TPB, 1) score_kernel(
    const int* __restrict__ labels, const float* __restrict__ W2,
    float* __restrict__ out)
{
    extern __shared__ float sm[];
    float* sp    = sm;                        // 2 * 8320
    float* qp    = sm + 2 * CHUNKF;           // 16*256 = 4096
    float* pbuf  = qp + QB * DIM;             // 16*16*32 = 8192
    float* tbuf  = pbuf + 16 * QB * 32;       // 16*32 = 512
    float* part  = tbuf + 16 * 32;            // 16*320 = 5120
    float* tpart = part + QB * NS;            // 320
    float* sacc  = tpart + NS;                // 320
    int*   lbl   = (int*)(sacc + QB * NWAY);  // 320

    const int tid  = threadIdx.x;
    const int warp = tid >> 5;               // d-team, 16 dims each
    const int lane = tid & 31;               // s within chunk
    const int qbase = blockIdx.x * QB;

    prefetch_chunk(sp, 0, tid);

    {
        const float4* qsrc = (const float4*)(g_qproj + qbase * DIM);
        float4* qpv = (float4*)qp;
        #pragma unroll
        for (int i = 0; i < 2; i++) qpv[tid + i * TPB] = qsrc[tid + i * TPB];
        if (tid < NS) lbl[tid] = labels[tid];
        if (tid < QB * NWAY) sacc[tid] = 0.f;
    }

    const int doff = warp * 16;              // this team's d-slice offset

    // hoist W2 slice: 4 x ulonglong2 (8 u64)
    u64 wx[4], wy[4];
    #pragma unroll
    for (int j = 0; j < 4; j++) {
        ulonglong2 wv = *(const ulonglong2*)(W2 + doff + j * 4);
        wx[j] = wv.x; wy[j] = wv.y;
    }

    for (int c = 0; c < 10; c++) {
        asm volatile("cp.async.wait_group 0;");
        __syncthreads();                      // chunk ready; pbuf/tbuf free
        float* cur = sp + (c & 1) * CHUNKF;
        if (c + 1 < 10) prefetch_chunk(sp + ((c + 1) & 1) * CHUNKF, c + 1, tid);

        const ulonglong2* srow = (const ulonglong2*)(cur + lane * SPAD + doff);
        float* pw = pbuf + (warp * QB) * 32;

        #pragma unroll
        for (int h = 0; h < 2; h++) {         // q-halves: 8 q per pass
            u64 ax[8], ay[8];
            #pragma unroll
            for (int qq = 0; qq < 8; qq++) { ax[qq] = 0ull; ay[qq] = 0ull; }
            u64 t0 = 0ull;                    // Ts slice (only used in h==0)

            #pragma unroll
            for (int j = 0; j < 4; j++) {
                ulonglong2 sv = srow[j];
                if (h == 0) {                 // fused Ts: sp . W2 over slice
                    t0 = fma2(sv.x, wx[j], t0);
                    t0 = fma2(sv.y, wy[j], t0);
                }
                #pragma unroll
                for (int qq = 0; qq < 8; qq++) {
                    const int q = h * 8 + qq;
                    ulonglong2 qv = *(const ulonglong2*)(qp + q * DIM + doff + j * 4);
                    u64 t;
                    t = add2(qv.x, sv.x) & ABSMASK; ax[qq] = fma2(t, wx[j], ax[qq]);
                    t = add2(qv.y, sv.y) & ABSMASK; ay[qq] = fma2(t, wy[j], ay[qq]);
                }
            }

            #pragma unroll
            for (int qq = 0; qq < 8; qq++)
                pw[(h * 8 + qq) * 32 + lane] =
                    (lo2(ax[qq]) + hi2(ax[qq])) + (lo2(ay[qq]) + hi2(ay[qq]));
            if (h == 0)
                tbuf[warp * 32 + lane] = lo2(t0) + hi2(t0);
        }

        __syncthreads();

        // tree reduce: thread (q = warp, sl = lane) sums 16 team partials
        {
            const int q = warp, sl = lane;
            float s = 0.f;
            #pragma unroll
            for (int w = 0; w < 16; w++)
                s += pbuf[(w * QB + q) * 32 + sl];
            part[q * NS + c * 32 + sl] = s;
        }
        if (warp == 0) {                      // Ts reduce
            float s = 0.f;
            #pragma unroll
            for (int w = 0; w < 16; w++)
                s += tbuf[w * 32 + lane];
            tpart[c * 32 + lane] = s;
        }
        // next top-of-loop __syncthreads separates reduce from next writes
    }
    __syncthreads();

    // ---- softmax: warp w owns q = w ----
    {
        const int q = warp;
        float v[10];
        #pragma unroll
        for (int c = 0; c < 10; c++)
            v[c] = 0.5f * (tpart[c * 32 + lane] + part[q * NS + c * 32 + lane]);

        float m = v[0];
        #pragma unroll
        for (int c = 1; c < 10; c++) m = fmaxf(m, v[c]);
        #pragma unroll
        for (int o = 16; o > 0; o >>= 1)
            m = fmaxf(m, __shfl_xor_sync(0xffffffffu, m, o));

        float l = 0.f;
        #pragma unroll
        for (int c = 0; c < 10; c++) {
            float ev = __expf(v[c] - m);
            l += ev;
            atomicAdd(&sacc[q * NWAY + lbl[c * 32 + lane]], ev);
        }
        #pragma unroll
        for (int o = 16; o > 0; o >>= 1)
            l += __shfl_xor_sync(0xffffffffu, l, o);
        const float inv = 1.f / l;
        __syncwarp();

        if (lane < NWAY)
            out[(qbase + q) * NWAY + lane] = sacc[q * NWAY + lane] * inv;
    }
}

// ---------------------------------------------------------------------------
extern "C" void kernel_launch(void* const* d_in, const int* in_sizes, int n_in,
                              void* d_out, int out_size)
{
    (void)in_sizes; (void)n_in; (void)out_size;
    const float* support = (const float*)d_in[0];
    const float* query   = (const float*)d_in[1];
    const int*   labels  = (const int*)d_in[2];
    const float* W1      = (const float*)d_in[3];
    const float* b1      = (const float*)d_in[4];
    const float* W2      = (const float*)d_in[5];
    float* out = (float*)d_out;

    const int proj_smem = (2 * ASTG) * 8 + (2 * BSTG) * 4;  // 101376 B
    cudaFuncSetAttribute(proj_kernel,
                         cudaFuncAttributeMaxDynamicSharedMemorySize, proj_smem);
    proj_kernel<<<dim3(4, 37), 256, proj_smem>>>(support, query, W1, b1);

    const int smem_bytes =
        (2 * CHUNKF + QB * DIM + 16 * QB * 32 + 16 * 32 + QB * NS + NS
         + QB * NWAY) * 4 + NS * 4;
    cudaFuncSetAttribute(score_kernel,
                         cudaFuncAttributeMaxDynamicSharedMemorySize, smem_bytes);
    score_kernel<<<NQ / QB, TPB, smem_bytes>>>(labels, W2, out);
}